// round 5
// baseline (speedup 1.0000x reference)
#include <cuda_runtime.h>
#include <cuda_bf16.h>
#include <math.h>
#include <stdint.h>

// Problem constants
#define B_DIM     32
#define S_DIM     2048
#define ROWS      65536
#define F_DIM     8
#define D_NODE    128
#define D_K       192
#define D_OUT     64
#define N_BT      64
#define N_ET      50
#define N_EQ      100

#define OFF_BT    192
#define OFF_POP   224
#define OFF_ET    240
#define OFF_EQ    272

#define THREADS        256
#define WARPS          8
#define ROWS_PER_WARP  16
#define TILE_M         128           // rows per CTA
#define NK2            96            // 192 k-values as 96 pairs

// smem layout (bytes)
#define SM_W      0                  // 96*32 float4 = 49152
#define SM_V      49152              // 8 warps * 12288 B
#define SM_CNT    147456             // 128 floats
#define SMEM_BYTES 147968

// Scratch (no cudaMalloc allowed)
__device__ float4 g_Wq[NK2 * 32];    // packed {W[2k][j],W[2k][j+32],W[2k+1][j],W[2k+1][j+32]}
__device__ float g_btype_proj[N_BT * D_OUT];
__device__ float g_etype_proj[N_ET * D_OUT];
__device__ float g_equip_proj[N_EQ * D_OUT];
__device__ float g_pv0[D_OUT];
__device__ float g_pv1[D_OUT];

// ---------------------------------------------------------------------------
// f32x2 packed helpers (FFMA2 path — PTX-only)
// ---------------------------------------------------------------------------
__device__ __forceinline__ unsigned long long fma2(unsigned long long a,
                                                   unsigned long long b,
                                                   unsigned long long c) {
    unsigned long long d;
    asm("fma.rn.f32x2 %0, %1, %2, %3;" : "=l"(d) : "l"(a), "l"(b), "l"(c));
    return d;
}
__device__ __forceinline__ unsigned long long bcast2(float x) {
    unsigned long long d;
    unsigned int xi = __float_as_uint(x);
    asm("mov.b64 %0, {%1, %1};" : "=l"(d) : "r"(xi));
    return d;
}
__device__ __forceinline__ void unpack2(unsigned long long v, float& lo, float& hi) {
    unsigned int a, b;
    asm("mov.b64 {%0, %1}, %2;" : "=r"(a), "=r"(b) : "l"(v));
    lo = __uint_as_float(a);
    hi = __uint_as_float(b);
}

// ---------------------------------------------------------------------------
// Precompute: project small-vocab tables into output space + pack W
// grid = 215 table blocks + 96 W-pack blocks = 311
// ---------------------------------------------------------------------------
__global__ void precompute_tables(const float* __restrict__ btype_table,
                                  const float* __restrict__ etype_table,
                                  const float* __restrict__ equip_table,
                                  const float* __restrict__ pop_w,
                                  const float* __restrict__ pop_b,
                                  const float* __restrict__ proj_w,
                                  const float* __restrict__ proj_b) {
    int j = threadIdx.x;
    int n = blockIdx.x;
    if (n < N_BT) {
        float a = 0.f;
        #pragma unroll
        for (int d = 0; d < 32; ++d)
            a += btype_table[n * 32 + d] * proj_w[(OFF_BT + d) * D_OUT + j];
        g_btype_proj[n * D_OUT + j] = a;
    } else if (n < N_BT + N_ET) {
        int m = n - N_BT;
        float a = 0.f;
        #pragma unroll
        for (int d = 0; d < 32; ++d)
            a += etype_table[m * 32 + d] * proj_w[(OFF_ET + d) * D_OUT + j];
        g_etype_proj[m * D_OUT + j] = a;
    } else if (n < N_BT + N_ET + N_EQ) {
        int m = n - N_BT - N_ET;
        float a = 0.f;
        #pragma unroll
        for (int d = 0; d < 32; ++d)
            a += equip_table[m * 32 + d] * proj_w[(OFF_EQ + d) * D_OUT + j];
        g_equip_proj[m * D_OUT + j] = a;
    } else if (n == N_BT + N_ET + N_EQ) {
        float a0 = 0.f, a1 = 0.f;
        #pragma unroll
        for (int d = 0; d < 16; ++d) {
            float w = proj_w[(OFF_POP + d) * D_OUT + j];
            a0 += pop_w[d] * w;
            a1 += pop_b[d] * w;
        }
        g_pv0[j] = a0;
        g_pv1[j] = a1 + proj_b[j];
    } else {
        int k2 = n - (N_BT + N_ET + N_EQ + 1);     // 0..95
        if (j < 32) {
            const float* r0 = proj_w + (2 * k2)     * D_OUT;
            const float* r1 = proj_w + (2 * k2 + 1) * D_OUT;
            g_Wq[k2 * 32 + j] = make_float4(r0[j], r0[j + 32], r1[j], r1[j + 32]);
        }
    }
}

// ---------------------------------------------------------------------------
// Main kernel: 256 threads / 8 warps; each warp handles 16 rows.
//
// Per-warp v buffer (12288 B): for (k2, rp) a 16B record
//   { v[2rp][2k2], v[2rp+1][2k2], v[2rp][2k2+1], v[2rp+1][2k2+1] }
// at byte  (k2*128 + rp*16) ^ (((k2>>1)&7) << 4)
// Phase 2 reads it as one LDS.128 broadcast (2 b64 operands for FFMA2).
// ---------------------------------------------------------------------------
__global__ void __launch_bounds__(THREADS)
combined_embedding_kernel(const int*   __restrict__ nbr_ids,
                          const float* __restrict__ time_feat,
                          const int*   __restrict__ bt_ids,
                          const float* __restrict__ counts,
                          const float* __restrict__ population,
                          const int*   __restrict__ et_ids,
                          const int*   __restrict__ eq_ids,
                          const float* __restrict__ node2vec,
                          const float* __restrict__ t2v_w,
                          const float* __restrict__ t2v_b,
                          float*       __restrict__ out) {
    extern __shared__ char smem[];
    float4* Wsm      = (float4*)(smem + SM_W);
    char*   vall     = smem + SM_V;
    float*  counts_s = (float*)(smem + SM_CNT);

    const int tid  = threadIdx.x;
    const int lane = tid & 31;
    const int warp = tid >> 5;
    const int ctabase = blockIdx.x * TILE_M;
    const int rowbase = ctabase + warp * ROWS_PER_WARP;

    // --- stage packed W (12 LDG.128 + STS.128 per thread) ---
    #pragma unroll
    for (int i = 0; i < 12; ++i)
        Wsm[i * THREADS + tid] = g_Wq[i * THREADS + tid];

    // --- counts_sum for this CTA's 128 s-values ---
    if (tid < TILE_M) {
        int sg = (ctabase & (S_DIM - 1)) + tid;
        float a = 0.f;
        #pragma unroll
        for (int b = 0; b < B_DIM; ++b) a += counts[b * S_DIM + sg];
        counts_s[tid] = a;
    }
    __syncthreads();

    char* vw = vall + warp * 12288;

    // per-lane t2v constants: this lane produces t2v elems kk=lane, kk=32+lane
    const float tw1 = t2v_w[lane],      tb1 = t2v_b[lane];
    const float tw2 = t2v_w[32 + lane], tb2 = t2v_b[32 + lane];
    const int f1 = lane >> 3;              // time-feature index for kk=lane
    const bool do_sin = (lane & 7) != 0;

    // hoist all 16 neighborhood ids (independent broadcast LDGs -> MLP)
    int nid[ROWS_PER_WARP];
    #pragma unroll
    for (int r = 0; r < ROWS_PER_WARP; ++r) nid[r] = nbr_ids[rowbase + r];

    // --- Phase 1: build packed v buffer, one row-pair at a time ---
    #pragma unroll
    for (int rp = 0; rp < 8; ++rp) {
        int row0 = rowbase + 2 * rp;
        int row1 = row0 + 1;

        // spatial: lane owns k = 4*lane .. 4*lane+3 for both rows
        float4 e = ((const float4*)(node2vec + (size_t)nid[2 * rp]     * D_NODE))[lane];
        float4 o = ((const float4*)(node2vec + (size_t)nid[2 * rp + 1] * D_NODE))[lane];
        // k2 = 2*lane (k=4l,4l+1) and 2*lane+1 (k=4l+2,4l+3); swizzle key = lane&7
        char* pa = vw + (2 * lane) * 128 + ((rp * 16) ^ ((lane & 7) << 4));
        *(float4*)pa         = make_float4(e.x, o.x, e.y, o.y);
        *(float4*)(pa + 128) = make_float4(e.z, o.z, e.w, o.w);

        // t2v: lane owns kk=lane (k=128+lane) and kk=32+lane (k=160+lane)
        float x10 = time_feat[row0 * F_DIM + f1];
        float x11 = time_feat[row1 * F_DIM + f1];
        float x20 = time_feat[row0 * F_DIM + 4 + f1];
        float x21 = time_feat[row1 * F_DIM + 4 + f1];
        float ae1 = fmaf(x10, tw1, tb1), ao1 = fmaf(x11, tw1, tb1);
        float ae2 = fmaf(x20, tw2, tb2), ao2 = fmaf(x21, tw2, tb2);
        float e1 = do_sin ? __sinf(ae1) : ae1;
        float o1 = do_sin ? __sinf(ao1) : ao1;
        float e2 = do_sin ? __sinf(ae2) : ae2;
        float o2 = do_sin ? __sinf(ao2) : ao2;
        // k=128+lane -> k2 = 64+(lane>>1); k=160+lane -> k2 = 80+(lane>>1)
        // swizzle key for both = (lane>>2)&7; odd k -> +8 within the record
        int soff = ((rp * 16) ^ (((lane >> 2) & 7) << 4)) + ((lane & 1) << 3);
        *(float2*)(vw + (64 + (lane >> 1)) * 128 + soff) = make_float2(e1, o1);
        *(float2*)(vw + (80 + (lane >> 1)) * 128 + soff) = make_float2(e2, o2);
    }
    __syncwarp();

    // --- Phase 2: 192x64 matvec for 16 rows via FFMA2 ---
    // acc0[rp] = packed (out[2rp][j], out[2rp+1][j]); acc1 for j+32
    unsigned long long acc0[8], acc1[8];
    #pragma unroll
    for (int rp = 0; rp < 8; ++rp) { acc0[rp] = 0ull; acc1[rp] = 0ull; }

    const float4* Wl = Wsm + lane;
    #pragma unroll 4
    for (int k2 = 0; k2 < NK2; ++k2) {
        float4 w = Wl[k2 * 32];
        unsigned long long wx = bcast2(w.x);   // W[2k2][j]
        unsigned long long wy = bcast2(w.y);   // W[2k2][j+32]
        unsigned long long wz = bcast2(w.z);   // W[2k2+1][j]
        unsigned long long ww = bcast2(w.w);   // W[2k2+1][j+32]
        const char* vbase = vw + k2 * 128;
        int swz = ((k2 >> 1) & 7) << 4;
        #pragma unroll
        for (int rp = 0; rp < 8; ++rp) {
            ulonglong2 vv = *(const ulonglong2*)(vbase + ((rp * 16) ^ swz));
            acc0[rp] = fma2(vv.x, wx, acc0[rp]);
            acc1[rp] = fma2(vv.x, wy, acc1[rp]);
            acc0[rp] = fma2(vv.y, wz, acc0[rp]);
            acc1[rp] = fma2(vv.y, ww, acc1[rp]);
        }
    }

    // --- Epilogue: add pre-projected lookup contributions, store ---
    #pragma unroll
    for (int rp = 0; rp < 8; ++rp) {
        float a0lo, a0hi, a1lo, a1hi;
        unpack2(acc0[rp], a0lo, a0hi);
        unpack2(acc1[rp], a1lo, a1hi);
        #pragma unroll
        for (int h = 0; h < 2; ++h) {
            int r   = 2 * rp + h;
            int row = rowbase + r;
            float accj  = h ? a0hi : a0lo;
            float accj2 = h ? a1hi : a1lo;
            float c = counts_s[row & (TILE_M - 1)];
            float p = population[row];
            int bt = bt_ids[row], et = et_ids[row], eq = eq_ids[row];

            float o0 = accj
                     + c * g_btype_proj[bt * D_OUT + lane]
                     + g_etype_proj[et * D_OUT + lane]
                     + g_equip_proj[eq * D_OUT + lane]
                     + p * g_pv0[lane] + g_pv1[lane];
            float o1 = accj2
                     + c * g_btype_proj[bt * D_OUT + 32 + lane]
                     + g_etype_proj[et * D_OUT + 32 + lane]
                     + g_equip_proj[eq * D_OUT + 32 + lane]
                     + p * g_pv0[32 + lane] + g_pv1[32 + lane];

            out[row * D_OUT + lane]      = o0;
            out[row * D_OUT + 32 + lane] = o1;
        }
    }
}

// ---------------------------------------------------------------------------
extern "C" void kernel_launch(void* const* d_in, const int* in_sizes, int n_in,
                              void* d_out, int out_size) {
    const int*   nbr     = (const int*)  d_in[0];
    const float* tfeat   = (const float*)d_in[1];
    const int*   bt      = (const int*)  d_in[2];
    const float* counts  = (const float*)d_in[3];
    const float* pop     = (const float*)d_in[4];
    const int*   et      = (const int*)  d_in[5];
    const int*   eq      = (const int*)  d_in[6];
    const float* n2v     = (const float*)d_in[7];
    const float* t2vw    = (const float*)d_in[8];
    const float* t2vb    = (const float*)d_in[9];
    const float* btt     = (const float*)d_in[10];
    const float* popw    = (const float*)d_in[11];
    const float* popb    = (const float*)d_in[12];
    const float* ett     = (const float*)d_in[13];
    const float* eqt     = (const float*)d_in[14];
    const float* pw      = (const float*)d_in[15];
    const float* pb      = (const float*)d_in[16];
    float*       out     = (float*)d_out;

    precompute_tables<<<N_BT + N_ET + N_EQ + 1 + NK2, 64>>>(
        btt, ett, eqt, popw, popb, pw, pb);

    cudaFuncSetAttribute(combined_embedding_kernel,
                         cudaFuncAttributeMaxDynamicSharedMemorySize, SMEM_BYTES);
    combined_embedding_kernel<<<ROWS / TILE_M, THREADS, SMEM_BYTES>>>(
        nbr, tfeat, bt, counts, pop, et, eq, n2v, t2vw, t2vb, out);
}

// round 6
// speedup vs baseline: 1.4018x; 1.4018x over previous
#include <cuda_runtime.h>
#include <cuda_bf16.h>
#include <math.h>
#include <stdint.h>

// Problem constants
#define B_DIM     32
#define S_DIM     2048
#define ROWS      65536
#define F_DIM     8
#define D_NODE    128
#define D_K       192
#define D_OUT     64
#define N_BT      64
#define N_ET      50
#define N_EQ      100

#define OFF_BT    192
#define OFF_POP   224
#define OFF_ET    240
#define OFF_EQ    272

#define THREADS        256
#define WARPS          8
#define ROWS_PER_WARP  8
#define TILE_M         64            // rows per CTA
#define NK2            96            // 192 k-values as 96 pairs

// v layout per warp: record for (k2, rp) = 16 bytes at  k2*80 + rp*16
//   {v[2rp][2k2], v[2rp+1][2k2], v[2rp][2k2+1], v[2rp+1][2k2+1]}
// stride 80 B keeps every record 16-aligned -> LDS.128 broadcast reads,
// pure affine addressing (no swizzle ALU in the hot loop).
#define VWARP_BYTES    (NK2 * 80)    // 7680

// smem layout (bytes)
#define SM_W      0                                  // 96*32 float4 = 49152
#define SM_V      49152
#define SM_CNT    (SM_V + WARPS * VWARP_BYTES)       // 110592, 64 floats
#define SMEM_BYTES (SM_CNT + 256)                    // 110848 -> 2 CTAs/SM

// Scratch (no cudaMalloc allowed)
__device__ float4 g_Wq[NK2 * 32];    // {W[2k][j],W[2k][j+32],W[2k+1][j],W[2k+1][j+32]}
__device__ float g_btype_proj[N_BT * D_OUT];
__device__ float g_etype_proj[N_ET * D_OUT];
__device__ float g_equip_proj[N_EQ * D_OUT];
__device__ float g_pv0[D_OUT];
__device__ float g_pv1[D_OUT];

// ---------------------------------------------------------------------------
// f32x2 packed helpers (FFMA2 path — PTX-only)
// ---------------------------------------------------------------------------
__device__ __forceinline__ unsigned long long fma2(unsigned long long a,
                                                   unsigned long long b,
                                                   unsigned long long c) {
    unsigned long long d;
    asm("fma.rn.f32x2 %0, %1, %2, %3;" : "=l"(d) : "l"(a), "l"(b), "l"(c));
    return d;
}
__device__ __forceinline__ unsigned long long bcast2(float x) {
    unsigned long long d;
    unsigned int xi = __float_as_uint(x);
    asm("mov.b64 %0, {%1, %1};" : "=l"(d) : "r"(xi));
    return d;
}
__device__ __forceinline__ void unpack2(unsigned long long v, float& lo, float& hi) {
    unsigned int a, b;
    asm("mov.b64 {%0, %1}, %2;" : "=r"(a), "=r"(b) : "l"(v));
    lo = __uint_as_float(a);
    hi = __uint_as_float(b);
}

// ---------------------------------------------------------------------------
// Precompute: project small-vocab tables into output space + pack W
// ---------------------------------------------------------------------------
__global__ void precompute_tables(const float* __restrict__ btype_table,
                                  const float* __restrict__ etype_table,
                                  const float* __restrict__ equip_table,
                                  const float* __restrict__ pop_w,
                                  const float* __restrict__ pop_b,
                                  const float* __restrict__ proj_w,
                                  const float* __restrict__ proj_b) {
    int j = threadIdx.x;
    int n = blockIdx.x;
    if (n < N_BT) {
        float a = 0.f;
        #pragma unroll
        for (int d = 0; d < 32; ++d)
            a += btype_table[n * 32 + d] * proj_w[(OFF_BT + d) * D_OUT + j];
        g_btype_proj[n * D_OUT + j] = a;
    } else if (n < N_BT + N_ET) {
        int m = n - N_BT;
        float a = 0.f;
        #pragma unroll
        for (int d = 0; d < 32; ++d)
            a += etype_table[m * 32 + d] * proj_w[(OFF_ET + d) * D_OUT + j];
        g_etype_proj[m * D_OUT + j] = a;
    } else if (n < N_BT + N_ET + N_EQ) {
        int m = n - N_BT - N_ET;
        float a = 0.f;
        #pragma unroll
        for (int d = 0; d < 32; ++d)
            a += equip_table[m * 32 + d] * proj_w[(OFF_EQ + d) * D_OUT + j];
        g_equip_proj[m * D_OUT + j] = a;
    } else if (n == N_BT + N_ET + N_EQ) {
        float a0 = 0.f, a1 = 0.f;
        #pragma unroll
        for (int d = 0; d < 16; ++d) {
            float w = proj_w[(OFF_POP + d) * D_OUT + j];
            a0 += pop_w[d] * w;
            a1 += pop_b[d] * w;
        }
        g_pv0[j] = a0;
        g_pv1[j] = a1 + proj_b[j];
    } else {
        int k2 = n - (N_BT + N_ET + N_EQ + 1);     // 0..95
        if (j < 32) {
            const float* r0 = proj_w + (2 * k2)     * D_OUT;
            const float* r1 = proj_w + (2 * k2 + 1) * D_OUT;
            g_Wq[k2 * 32 + j] = make_float4(r0[j], r0[j + 32], r1[j], r1[j + 32]);
        }
    }
}

// ---------------------------------------------------------------------------
// Main kernel: 256 threads / 8 warps, 8 rows per warp, 2 CTAs/SM.
// ---------------------------------------------------------------------------
__global__ void __launch_bounds__(THREADS, 2)
combined_embedding_kernel(const int*   __restrict__ nbr_ids,
                          const float* __restrict__ time_feat,
                          const int*   __restrict__ bt_ids,
                          const float* __restrict__ counts,
                          const float* __restrict__ population,
                          const int*   __restrict__ et_ids,
                          const int*   __restrict__ eq_ids,
                          const float* __restrict__ node2vec,
                          const float* __restrict__ t2v_w,
                          const float* __restrict__ t2v_b,
                          float*       __restrict__ out) {
    extern __shared__ char smem[];
    float4* Wsm      = (float4*)(smem + SM_W);
    float*  counts_s = (float*)(smem + SM_CNT);

    const int tid  = threadIdx.x;
    const int lane = tid & 31;
    const int warp = tid >> 5;
    const int ctabase = blockIdx.x * TILE_M;
    const int rowbase = ctabase + warp * ROWS_PER_WARP;

    // --- stage packed W (12 LDG.128 + STS.128 per thread) ---
    #pragma unroll
    for (int i = 0; i < 12; ++i)
        Wsm[i * THREADS + tid] = g_Wq[i * THREADS + tid];

    // --- counts_sum for this CTA's 64 s-values (4 threads per s) ---
    {
        int sl = tid >> 2, q = tid & 3;
        int sg = (ctabase & (S_DIM - 1)) + sl;
        float p = 0.f;
        #pragma unroll
        for (int i = 0; i < 8; ++i) p += counts[(q * 8 + i) * S_DIM + sg];
        p += __shfl_xor_sync(0xffffffffu, p, 1);
        p += __shfl_xor_sync(0xffffffffu, p, 2);
        if (q == 0) counts_s[sl] = p;
    }
    __syncthreads();

    char* vw = smem + SM_V + warp * VWARP_BYTES;

    // per-lane t2v constants: lane produces t2v elems kk=lane and kk=32+lane
    const float tw1 = t2v_w[lane],      tb1 = t2v_b[lane];
    const float tw2 = t2v_w[32 + lane], tb2 = t2v_b[32 + lane];
    const int  f1 = lane >> 3;
    const bool do_sin = (lane & 7) != 0;

    // hoist neighborhood ids (independent broadcast LDGs -> MLP)
    int nid[ROWS_PER_WARP];
    #pragma unroll
    for (int r = 0; r < ROWS_PER_WARP; ++r) nid[r] = nbr_ids[rowbase + r];

    // --- Phase 1: build v buffer, one row-pair at a time ---
    #pragma unroll
    for (int rp = 0; rp < 4; ++rp) {
        int row0 = rowbase + 2 * rp;
        int row1 = row0 + 1;

        // spatial: lane owns k = 4*lane .. 4*lane+3 (k2 = 2*lane, 2*lane+1)
        float4 e = ((const float4*)(node2vec + (size_t)nid[2 * rp]     * D_NODE))[lane];
        float4 o = ((const float4*)(node2vec + (size_t)nid[2 * rp + 1] * D_NODE))[lane];
        char* p0 = vw + lane * 160 + rp * 16;
        *(float4*)p0        = make_float4(e.x, o.x, e.y, o.y);
        *(float4*)(p0 + 80) = make_float4(e.z, o.z, e.w, o.w);

        // t2v: lane owns kk=lane (k=128+lane) and kk=32+lane (k=160+lane)
        float x10 = time_feat[row0 * F_DIM + f1];
        float x11 = time_feat[row1 * F_DIM + f1];
        float x20 = time_feat[row0 * F_DIM + 4 + f1];
        float x21 = time_feat[row1 * F_DIM + 4 + f1];
        float ae1 = fmaf(x10, tw1, tb1), ao1 = fmaf(x11, tw1, tb1);
        float ae2 = fmaf(x20, tw2, tb2), ao2 = fmaf(x21, tw2, tb2);
        float e1 = do_sin ? __sinf(ae1) : ae1;
        float o1 = do_sin ? __sinf(ao1) : ao1;
        float e2 = do_sin ? __sinf(ae2) : ae2;
        float o2 = do_sin ? __sinf(ao2) : ao2;
        int soff = rp * 16 + ((lane & 1) << 3);
        *(float2*)(vw + (64 + (lane >> 1)) * 80 + soff) = make_float2(e1, o1);
        *(float2*)(vw + (80 + (lane >> 1)) * 80 + soff) = make_float2(e2, o2);
    }
    __syncwarp();

    // --- Phase 2: 192x64 matvec for 8 rows via FFMA2 ---
    // acc0[rp] = packed (out[2rp][j], out[2rp+1][j]); acc1 for j+32
    unsigned long long acc0[4] = {0ull, 0ull, 0ull, 0ull};
    unsigned long long acc1[4] = {0ull, 0ull, 0ull, 0ull};

    const float4* Wl = Wsm + lane;
    #pragma unroll 4
    for (int k2 = 0; k2 < NK2; ++k2) {
        float4 w = Wl[k2 * 32];
        unsigned long long wx = bcast2(w.x);   // W[2k2][j]
        unsigned long long wy = bcast2(w.y);   // W[2k2][j+32]
        unsigned long long wz = bcast2(w.z);   // W[2k2+1][j]
        unsigned long long ww = bcast2(w.w);   // W[2k2+1][j+32]
        const char* vb = vw + k2 * 80;
        #pragma unroll
        for (int rp = 0; rp < 4; ++rp) {
            ulonglong2 vv = *(const ulonglong2*)(vb + rp * 16);
            acc0[rp] = fma2(vv.x, wx, acc0[rp]);
            acc1[rp] = fma2(vv.x, wy, acc1[rp]);
            acc0[rp] = fma2(vv.y, wz, acc0[rp]);
            acc1[rp] = fma2(vv.y, ww, acc1[rp]);
        }
    }

    // --- Epilogue: add pre-projected lookup contributions, store ---
    #pragma unroll
    for (int rp = 0; rp < 4; ++rp) {
        float a0lo, a0hi, a1lo, a1hi;
        unpack2(acc0[rp], a0lo, a0hi);
        unpack2(acc1[rp], a1lo, a1hi);
        #pragma unroll
        for (int h = 0; h < 2; ++h) {
            int r   = 2 * rp + h;
            int row = rowbase + r;
            float accj  = h ? a0hi : a0lo;
            float accj2 = h ? a1hi : a1lo;
            float c = counts_s[row & (TILE_M - 1)];
            float p = population[row];
            int bt = bt_ids[row], et = et_ids[row], eq = eq_ids[row];

            float o0 = accj
                     + c * g_btype_proj[bt * D_OUT + lane]
                     + g_etype_proj[et * D_OUT + lane]
                     + g_equip_proj[eq * D_OUT + lane]
                     + p * g_pv0[lane] + g_pv1[lane];
            float o1 = accj2
                     + c * g_btype_proj[bt * D_OUT + 32 + lane]
                     + g_etype_proj[et * D_OUT + 32 + lane]
                     + g_equip_proj[eq * D_OUT + 32 + lane]
                     + p * g_pv0[32 + lane] + g_pv1[32 + lane];

            out[row * D_OUT + lane]      = o0;
            out[row * D_OUT + 32 + lane] = o1;
        }
    }
}

// ---------------------------------------------------------------------------
extern "C" void kernel_launch(void* const* d_in, const int* in_sizes, int n_in,
                              void* d_out, int out_size) {
    const int*   nbr     = (const int*)  d_in[0];
    const float* tfeat   = (const float*)d_in[1];
    const int*   bt      = (const int*)  d_in[2];
    const float* counts  = (const float*)d_in[3];
    const float* pop     = (const float*)d_in[4];
    const int*   et      = (const int*)  d_in[5];
    const int*   eq      = (const int*)  d_in[6];
    const float* n2v     = (const float*)d_in[7];
    const float* t2vw    = (const float*)d_in[8];
    const float* t2vb    = (const float*)d_in[9];
    const float* btt     = (const float*)d_in[10];
    const float* popw    = (const float*)d_in[11];
    const float* popb    = (const float*)d_in[12];
    const float* ett     = (const float*)d_in[13];
    const float* eqt     = (const float*)d_in[14];
    const float* pw      = (const float*)d_in[15];
    const float* pb      = (const float*)d_in[16];
    float*       out     = (float*)d_out;

    precompute_tables<<<N_BT + N_ET + N_EQ + 1 + NK2, 64>>>(
        btt, ett, eqt, popw, popb, pw, pb);

    cudaFuncSetAttribute(combined_embedding_kernel,
                         cudaFuncAttributeMaxDynamicSharedMemorySize, SMEM_BYTES);
    combined_embedding_kernel<<<ROWS / TILE_M, THREADS, SMEM_BYTES>>>(
        nbr, tfeat, bt, counts, pop, et, eq, n2v, t2vw, t2vb, out);
}